// round 9
// baseline (speedup 1.0000x reference)
#include <cuda_runtime.h>
#include <cuda_fp16.h>
#include <cstdint>

#define THREADS 256
#define DEG     16
#define DD      128
#define NPB     128     // nodes per GEMM block
#define MAXN    100096

// GEMM kernel smem: single fp16 A tile, XOR-swizzled rows of 256B
#define SM_A     0
#define SM_TOTAL 32768

// W in mma-B-fragment layout, fp16 hi/lo interleaved
__device__ uint4 gB[8 * 128 * 4];
// fp16 node features (25.6 MB), row = 16 uint4
__device__ uint4 gFeat16[MAXN * DD / 8];
// packed edges: {col0, wn0, col1, wn1} per uint4, 8 per node (12.8 MB)
__device__ uint4 gEdge4[MAXN * DEG / 2];
// fp16 aggregated features (25.6 MB)
__device__ uint4 gAgg[MAXN * DD / 8];

__device__ __forceinline__ void split_f16(float x, unsigned short& h, unsigned short& l) {
    __half hh = __float2half_rn(x);
    float r = x - __half2float(hh);
    __half ll = __float2half_rn(r);
    h = __half_as_ushort(hh);
    l = __half_as_ushort(ll);
}

__device__ __forceinline__ int a_off(int row, int chunk) {
    return row * 256 + ((chunk ^ (row & 7)) << 4);
}

__device__ __forceinline__ uint32_t smem_u32(const void* p) {
    uint32_t a;
    asm("{ .reg .u64 t; cvta.to.shared.u64 t, %1; cvt.u32.u64 %0, t; }" : "=r"(a) : "l"(p));
    return a;
}

__device__ __forceinline__ void ldmatrix_x4(uint32_t& r0, uint32_t& r1,
                                            uint32_t& r2, uint32_t& r3, uint32_t addr) {
    asm volatile("ldmatrix.sync.aligned.m8n8.x4.shared.b16 {%0,%1,%2,%3}, [%4];"
                 : "=r"(r0), "=r"(r1), "=r"(r2), "=r"(r3) : "r"(addr));
}

__device__ __forceinline__ void mma_f16(float& d0, float& d1, float& d2, float& d3,
                                        uint32_t a0, uint32_t a1, uint32_t a2, uint32_t a3,
                                        uint32_t b0, uint32_t b1) {
    asm volatile("mma.sync.aligned.m16n8k16.row.col.f32.f16.f16.f32 "
                 "{%0,%1,%2,%3}, {%4,%5,%6,%7}, {%8,%9}, {%0,%1,%2,%3};"
                 : "+f"(d0), "+f"(d1), "+f"(d2), "+f"(d3)
                 : "r"(a0), "r"(a1), "r"(a2), "r"(a3), "r"(b0), "r"(b1));
}

__device__ __forceinline__ void fma2_h2(unsigned long long& acc,
                                        unsigned long long w2, unsigned h2bits) {
    const float2 f = __half22float2(*(const __half2*)&h2bits);
    unsigned long long v;
    asm("mov.b64 %0, {%1, %2};" : "=l"(v) : "f"(f.x), "f"(f.y));
    asm("fma.rn.f32x2 %0, %1, %2, %0;" : "+l"(acc) : "l"(w2), "l"(v));
}
__device__ __forceinline__ void unpack64(unsigned long long v, float& lo, float& hi) {
    asm("mov.b64 {%0, %1}, %2;" : "=f"(lo), "=f"(hi) : "l"(v));
}

// ---- fused prep: feat fp32->fp16 | W fp16-split | edge packing ----
__global__ void __launch_bounds__(256)
prep_all(const float* __restrict__ feat, const float* __restrict__ Wg,
         const int* __restrict__ rows32, const char* __restrict__ cols_raw,
         const float* __restrict__ ew,
         int nblk_feat, int nblk_w, int total16, int N)
{
    const int b = (int)blockIdx.x;
    if (b < nblk_feat) {
        const int i = b * 256 + threadIdx.x;             // unit = 16 floats
        if (i >= total16) return;
        const float4* src = (const float4*)feat + i * 4;
        uint4* dst = gFeat16 + i * 2;
        float4 v0 = __ldg(src + 0);
        float4 v1 = __ldg(src + 1);
        float4 v2 = __ldg(src + 2);
        float4 v3 = __ldg(src + 3);
        __half2 a0 = __floats2half2_rn(v0.x, v0.y), a1 = __floats2half2_rn(v0.z, v0.w);
        __half2 a2 = __floats2half2_rn(v1.x, v1.y), a3 = __floats2half2_rn(v1.z, v1.w);
        __half2 a4 = __floats2half2_rn(v2.x, v2.y), a5 = __floats2half2_rn(v2.z, v2.w);
        __half2 a6 = __floats2half2_rn(v3.x, v3.y), a7 = __floats2half2_rn(v3.z, v3.w);
        dst[0] = make_uint4(*(unsigned*)&a0, *(unsigned*)&a1, *(unsigned*)&a2, *(unsigned*)&a3);
        dst[1] = make_uint4(*(unsigned*)&a4, *(unsigned*)&a5, *(unsigned*)&a6, *(unsigned*)&a7);
    } else if (b < nblk_feat + nblk_w) {
        const int e = (b - nblk_feat) * 256 + threadIdx.x;   // 0..4095
        if (e >= 8 * 128 * 4) return;
        const int kc = e >> 9;
        const int n  = (e >> 2) & 127;
        const int q  = e & 3;
        const int k0 = kc * 16 + 2 * q;
        unsigned short h[4], l[4];
        split_f16(__ldg(Wg + (k0    ) * DD + n), h[0], l[0]);
        split_f16(__ldg(Wg + (k0 + 1) * DD + n), h[1], l[1]);
        split_f16(__ldg(Wg + (k0 + 8) * DD + n), h[2], l[2]);
        split_f16(__ldg(Wg + (k0 + 9) * DD + n), h[3], l[3]);
        gB[e] = make_uint4((unsigned)h[0] | ((unsigned)h[1] << 16),
                           (unsigned)h[2] | ((unsigned)h[3] << 16),
                           (unsigned)l[0] | ((unsigned)l[1] << 16),
                           (unsigned)l[2] | ((unsigned)l[3] << 16));
    } else {
        // edge packing: one thread per node
        const int node = (b - nblk_feat - nblk_w) * 256 + threadIdx.x;
        if (node >= N) return;
        const bool idx64 = (__ldg(rows32 + 33) == 0);
        const long long* cols64 = (const long long*)cols_raw;
        const int*       cols32 = (const int*)cols_raw;
        const long long eb = (long long)node * DEG;
        int   c[DEG];
        float w[DEG];
        float den = 0.f;
        #pragma unroll
        for (int e = 0; e < DEG; e++) {
            c[e] = idx64 ? (int)__ldg(cols64 + eb + e) : __ldg(cols32 + eb + e);
            w[e] = __ldg(ew + eb + e);
            den += w[e];
        }
        const float inv = 1.f / den;
        uint4* dst = gEdge4 + node * (DEG / 2);
        #pragma unroll
        for (int p = 0; p < DEG / 2; p++) {
            const float w0 = w[2 * p] * inv, w1 = w[2 * p + 1] * inv;
            dst[p] = make_uint4((unsigned)c[2 * p], __float_as_uint(w0),
                                (unsigned)c[2 * p + 1], __float_as_uint(w1));
        }
    }
}

// ---- gather kernel: half-warp per node, lane owns 8 features; no smem ----
__global__ void __launch_bounds__(256)
gcn_gather(int N)
{
    const int tid  = threadIdx.x;
    const int wid  = tid >> 5;
    const int lane = tid & 31;
    const int s    = lane & 15;
    const int hb   = lane >> 4;

    const int node = blockIdx.x * 16 + wid * 2 + hb;
    if (node >= N) return;

    const uint4* __restrict__ desc = gEdge4 + node * (DEG / 2);
    unsigned long long acc[4] = {0ull, 0ull, 0ull, 0ull};

    #pragma unroll
    for (int p = 0; p < DEG / 2; p++) {
        const uint4 d = __ldg(desc + p);                 // {c0, w0, c1, w1} (uniform)
        const uint4 v0 = __ldg(gFeat16 + (size_t)d.x * 16 + s);
        const uint4 v1 = __ldg(gFeat16 + (size_t)d.z * 16 + s);
        unsigned long long w0, w1;
        asm("mov.b64 %0, {%1, %1};" : "=l"(w0) : "r"(d.y));
        asm("mov.b64 %0, {%1, %1};" : "=l"(w1) : "r"(d.w));
        fma2_h2(acc[0], w0, v0.x);
        fma2_h2(acc[1], w0, v0.y);
        fma2_h2(acc[2], w0, v0.z);
        fma2_h2(acc[3], w0, v0.w);
        fma2_h2(acc[0], w1, v1.x);
        fma2_h2(acc[1], w1, v1.y);
        fma2_h2(acc[2], w1, v1.z);
        fma2_h2(acc[3], w1, v1.w);
    }

    float f[8];
    unpack64(acc[0], f[0], f[1]);
    unpack64(acc[1], f[2], f[3]);
    unpack64(acc[2], f[4], f[5]);
    unpack64(acc[3], f[6], f[7]);
    const __half2 p0 = __floats2half2_rn(f[0], f[1]);
    const __half2 p1 = __floats2half2_rn(f[2], f[3]);
    const __half2 p2 = __floats2half2_rn(f[4], f[5]);
    const __half2 p3 = __floats2half2_rn(f[6], f[7]);
    gAgg[(size_t)node * 16 + s] =
        make_uint4(*(const unsigned*)&p0, *(const unsigned*)&p1,
                   *(const unsigned*)&p2, *(const unsigned*)&p3);
}

// ---- GEMM kernel: stream agg tile -> smem -> HMMA -> bias+relu -> out ----
__global__ void __launch_bounds__(THREADS, 4)
gcn_gemm(const float* __restrict__ bias, float* __restrict__ out, int N)
{
    extern __shared__ char smem[];
    const int tid   = threadIdx.x;
    const int wid   = tid >> 5;
    const int lane  = tid & 31;
    const int node0 = blockIdx.x * NPB;

    // load A tile (128 rows x 16 uint4) coalesced, store swizzled
    #pragma unroll
    for (int i = 0; i < 8; i++) {
        const int idx = i * 256 + tid;           // 0..2047
        const int row = idx >> 4;
        const int ss  = idx & 15;
        const uint4 v = __ldg(gAgg + (size_t)node0 * 16 + idx);   // MAXN-padded: safe
        *(uint4*)(smem + SM_A + a_off(row, ss)) = v;
    }
    __syncthreads();

    const int m0 = wid * 16;
    const int mi = lane >> 3;
    const int mr = lane & 7;
    const int arow = m0 + ((mi & 1) << 3) + mr;
    const uint32_t sA = smem_u32(smem + SM_A);
    const int bq = (lane >> 2) * 4 + (lane & 3);

    const int r0 = node0 + m0 + (lane >> 2);
    const int cb = 2 * (lane & 3);

    #pragma unroll
    for (int half = 0; half < 2; half++) {
        float acc[8][4];
        #pragma unroll
        for (int nc = 0; nc < 8; nc++)
            acc[nc][0] = acc[nc][1] = acc[nc][2] = acc[nc][3] = 0.f;

        #pragma unroll
        for (int kc = 0; kc < 8; kc++) {
            const int chunk = kc * 2 + (mi >> 1);
            const uint32_t aaddr = (uint32_t)a_off(arow, chunk);
            uint32_t a0, a1, a2, a3;
            ldmatrix_x4(a0, a1, a2, a3, sA + aaddr);

            const uint4* __restrict__ bp = gB + kc * 512 + half * 256 + bq;
            #pragma unroll
            for (int nc = 0; nc < 8; nc++) {
                const uint4 v = __ldg(bp + nc * 32);
                mma_f16(acc[nc][0], acc[nc][1], acc[nc][2], acc[nc][3],
                        a0, a1, a2, a3, v.x, v.y);
                mma_f16(acc[nc][0], acc[nc][1], acc[nc][2], acc[nc][3],
                        a0, a1, a2, a3, v.z, v.w);
            }
        }

        #pragma unroll
        for (int nc = 0; nc < 8; nc++) {
            const int col = half * 64 + nc * 8 + cb;
            const float2 bv = __ldg((const float2*)(bias + col));
            if (r0 < N) {
                float2 o0;
                o0.x = fmaxf(acc[nc][0] + bv.x, 0.f);
                o0.y = fmaxf(acc[nc][1] + bv.y, 0.f);
                *(float2*)(out + (size_t)r0 * DD + col) = o0;
            }
            if (r0 + 8 < N) {
                float2 o1;
                o1.x = fmaxf(acc[nc][2] + bv.x, 0.f);
                o1.y = fmaxf(acc[nc][3] + bv.y, 0.f);
                *(float2*)(out + (size_t)(r0 + 8) * DD + col) = o1;
            }
        }
    }
}

extern "C" void kernel_launch(void* const* d_in, const int* in_sizes, int n_in,
                              void* d_out, int out_size)
{
    const float* feat = (const float*)d_in[0];
    const int*   rows = (const int*)d_in[1];
    const char*  cols = (const char*)d_in[2];
    const float* ew   = (const float*)d_in[3];
    const float* Wg   = (const float*)d_in[4];
    const float* bias = (const float*)d_in[5];
    float*       out  = (float*)d_out;

    const int N = in_sizes[0] / DD;

    const int total16   = N * DD / 16;
    const int nblk_feat = (total16 + 255) / 256;
    const int nblk_w    = (8 * 128 * 4 + 255) / 256;
    const int nblk_e    = (N + 255) / 256;
    prep_all<<<nblk_feat + nblk_w + nblk_e, 256>>>(feat, Wg, rows, cols, ew,
                                                   nblk_feat, nblk_w, total16, N);

    gcn_gather<<<(N + 15) / 16, 256>>>(N);

    cudaFuncSetAttribute(gcn_gemm, cudaFuncAttributeMaxDynamicSharedMemorySize, SM_TOTAL);
    gcn_gemm<<<(N + NPB - 1) / NPB, THREADS, SM_TOTAL>>>(bias, out, N);
}

// round 10
// speedup vs baseline: 1.0932x; 1.0932x over previous
#include <cuda_runtime.h>
#include <cuda_fp16.h>
#include <cstdint>

#define THREADS 256
#define DEG     16
#define DD      128
#define NPB     128     // nodes per GEMM block
#define MAXN    100096

// GEMM kernel smem: single fp16 A tile, XOR-swizzled rows of 256B
#define SM_A     0
#define SM_TOTAL 32768

// W in mma-B-fragment layout, fp16 hi/lo interleaved
__device__ uint4 gB[8 * 128 * 4];
// fp16 node features (25.6 MB), row = 16 uint4
__device__ uint4 gFeat16[MAXN * DD / 8];
// packed normalized edges: {col, w/den} per edge (12.8 MB)
__device__ uint2 gEdgeP[MAXN * DEG];
// fp16 aggregated features (25.6 MB)
__device__ uint4 gAgg[MAXN * DD / 8];

__device__ __forceinline__ void split_f16(float x, unsigned short& h, unsigned short& l) {
    __half hh = __float2half_rn(x);
    float r = x - __half2float(hh);
    __half ll = __float2half_rn(r);
    h = __half_as_ushort(hh);
    l = __half_as_ushort(ll);
}

__device__ __forceinline__ int a_off(int row, int chunk) {
    return row * 256 + ((chunk ^ (row & 7)) << 4);
}

__device__ __forceinline__ uint32_t smem_u32(const void* p) {
    uint32_t a;
    asm("{ .reg .u64 t; cvta.to.shared.u64 t, %1; cvt.u32.u64 %0, t; }" : "=r"(a) : "l"(p));
    return a;
}

__device__ __forceinline__ void ldmatrix_x4(uint32_t& r0, uint32_t& r1,
                                            uint32_t& r2, uint32_t& r3, uint32_t addr) {
    asm volatile("ldmatrix.sync.aligned.m8n8.x4.shared.b16 {%0,%1,%2,%3}, [%4];"
                 : "=r"(r0), "=r"(r1), "=r"(r2), "=r"(r3) : "r"(addr));
}

__device__ __forceinline__ void mma_f16(float& d0, float& d1, float& d2, float& d3,
                                        uint32_t a0, uint32_t a1, uint32_t a2, uint32_t a3,
                                        uint32_t b0, uint32_t b1) {
    asm volatile("mma.sync.aligned.m16n8k16.row.col.f32.f16.f16.f32 "
                 "{%0,%1,%2,%3}, {%4,%5,%6,%7}, {%8,%9}, {%0,%1,%2,%3};"
                 : "+f"(d0), "+f"(d1), "+f"(d2), "+f"(d3)
                 : "r"(a0), "r"(a1), "r"(a2), "r"(a3), "r"(b0), "r"(b1));
}

__device__ __forceinline__ void fma2_h2(unsigned long long& acc,
                                        unsigned long long w2, unsigned h2bits) {
    const float2 f = __half22float2(*(const __half2*)&h2bits);
    unsigned long long v;
    asm("mov.b64 %0, {%1, %2};" : "=l"(v) : "f"(f.x), "f"(f.y));
    asm("fma.rn.f32x2 %0, %1, %2, %0;" : "+l"(acc) : "l"(w2), "l"(v));
}
__device__ __forceinline__ void unpack64(unsigned long long v, float& lo, float& hi) {
    asm("mov.b64 {%0, %1}, %2;" : "=f"(lo), "=f"(hi) : "l"(v));
}

// ---- fused prep: feat fp32->fp16 | W fp16-split | coalesced edge packing ----
__global__ void __launch_bounds__(256)
prep_all(const float* __restrict__ feat, const float* __restrict__ Wg,
         const int* __restrict__ rows32, const char* __restrict__ cols_raw,
         const float* __restrict__ ew,
         int nblk_feat, int nblk_w, int total16, int N)
{
    const int b = (int)blockIdx.x;
    if (b < nblk_feat) {
        const int i = b * 256 + threadIdx.x;             // unit = 16 floats
        if (i >= total16) return;
        const float4* src = (const float4*)feat + i * 4;
        uint4* dst = gFeat16 + i * 2;
        float4 v0 = __ldg(src + 0);
        float4 v1 = __ldg(src + 1);
        float4 v2 = __ldg(src + 2);
        float4 v3 = __ldg(src + 3);
        __half2 a0 = __floats2half2_rn(v0.x, v0.y), a1 = __floats2half2_rn(v0.z, v0.w);
        __half2 a2 = __floats2half2_rn(v1.x, v1.y), a3 = __floats2half2_rn(v1.z, v1.w);
        __half2 a4 = __floats2half2_rn(v2.x, v2.y), a5 = __floats2half2_rn(v2.z, v2.w);
        __half2 a6 = __floats2half2_rn(v3.x, v3.y), a7 = __floats2half2_rn(v3.z, v3.w);
        dst[0] = make_uint4(*(unsigned*)&a0, *(unsigned*)&a1, *(unsigned*)&a2, *(unsigned*)&a3);
        dst[1] = make_uint4(*(unsigned*)&a4, *(unsigned*)&a5, *(unsigned*)&a6, *(unsigned*)&a7);
    } else if (b < nblk_feat + nblk_w) {
        const int e = (b - nblk_feat) * 256 + threadIdx.x;   // 0..4095
        if (e >= 8 * 128 * 4) return;
        const int kc = e >> 9;
        const int n  = (e >> 2) & 127;
        const int q  = e & 3;
        const int k0 = kc * 16 + 2 * q;
        unsigned short h[4], l[4];
        split_f16(__ldg(Wg + (k0    ) * DD + n), h[0], l[0]);
        split_f16(__ldg(Wg + (k0 + 1) * DD + n), h[1], l[1]);
        split_f16(__ldg(Wg + (k0 + 8) * DD + n), h[2], l[2]);
        split_f16(__ldg(Wg + (k0 + 9) * DD + n), h[3], l[3]);
        gB[e] = make_uint4((unsigned)h[0] | ((unsigned)h[1] << 16),
                           (unsigned)h[2] | ((unsigned)h[3] << 16),
                           (unsigned)l[0] | ((unsigned)l[1] << 16),
                           (unsigned)l[2] | ((unsigned)l[3] << 16));
    } else {
        // edge packing: half-warp per node, lane i owns edge i (coalesced)
        const int node0 = (b - nblk_feat - nblk_w) * 16 + ((int)threadIdx.x >> 4);
        const int li    = threadIdx.x & 15;
        const int node  = min(node0, N - 1);             // clamp; no early exit (shfl)
        const bool idx64 = (__ldg(rows32 + 33) == 0);
        const long long ei = (long long)node * DEG + li;
        const int   c = idx64 ? (int)__ldg((const long long*)cols_raw + ei)
                              : __ldg((const int*)cols_raw + ei);
        const float w = __ldg(ew + ei);
        float den = w;
        den += __shfl_xor_sync(0xffffffffu, den, 1);
        den += __shfl_xor_sync(0xffffffffu, den, 2);
        den += __shfl_xor_sync(0xffffffffu, den, 4);
        den += __shfl_xor_sync(0xffffffffu, den, 8);
        const float wn = w * __fdividef(1.f, den);
        if (node0 < N)
            gEdgeP[(size_t)node * DEG + li] = make_uint2((unsigned)c, __float_as_uint(wn));
    }
}

// ---- gather kernel: warp = 4 nodes (2 interleaved pairs); no smem ----
__global__ void __launch_bounds__(128)
gcn_gather(int N)
{
    const int tid  = threadIdx.x;
    const int wid  = tid >> 5;
    const int lane = tid & 31;
    const int s    = lane & 15;          // feature slice (8 halves = 1 uint4)
    const int hb   = lane >> 4;          // node select within pair

    const int base = (blockIdx.x * 4 + wid) * 4;
    const int nA0 = base + hb;           // pair 0
    const int nB0 = base + 2 + hb;       // pair 1
    const int nA = min(nA0, N - 1);
    const int nB = min(nB0, N - 1);

    const uint2* __restrict__ epA = gEdgeP + (size_t)nA * DEG;
    const uint2* __restrict__ epB = gEdgeP + (size_t)nB * DEG;

    unsigned long long aA[4] = {0ull, 0ull, 0ull, 0ull};
    unsigned long long aB[4] = {0ull, 0ull, 0ull, 0ull};

    #pragma unroll
    for (int e = 0; e < DEG; e++) {
        const uint2 dA = __ldg(epA + e);      // uniform within half-warp
        const uint2 dB = __ldg(epB + e);
        const uint4 vA = __ldg(gFeat16 + (size_t)dA.x * 16 + s);
        const uint4 vB = __ldg(gFeat16 + (size_t)dB.x * 16 + s);
        unsigned long long wA, wB;
        asm("mov.b64 %0, {%1, %1};" : "=l"(wA) : "r"(dA.y));
        asm("mov.b64 %0, {%1, %1};" : "=l"(wB) : "r"(dB.y));
        fma2_h2(aA[0], wA, vA.x);
        fma2_h2(aB[0], wB, vB.x);
        fma2_h2(aA[1], wA, vA.y);
        fma2_h2(aB[1], wB, vB.y);
        fma2_h2(aA[2], wA, vA.z);
        fma2_h2(aB[2], wB, vB.z);
        fma2_h2(aA[3], wA, vA.w);
        fma2_h2(aB[3], wB, vB.w);
    }

    float f[8];
    if (nA0 < N) {
        unpack64(aA[0], f[0], f[1]);
        unpack64(aA[1], f[2], f[3]);
        unpack64(aA[2], f[4], f[5]);
        unpack64(aA[3], f[6], f[7]);
        const __half2 p0 = __floats2half2_rn(f[0], f[1]);
        const __half2 p1 = __floats2half2_rn(f[2], f[3]);
        const __half2 p2 = __floats2half2_rn(f[4], f[5]);
        const __half2 p3 = __floats2half2_rn(f[6], f[7]);
        gAgg[(size_t)nA * 16 + s] =
            make_uint4(*(const unsigned*)&p0, *(const unsigned*)&p1,
                       *(const unsigned*)&p2, *(const unsigned*)&p3);
    }
    if (nB0 < N) {
        unpack64(aB[0], f[0], f[1]);
        unpack64(aB[1], f[2], f[3]);
        unpack64(aB[2], f[4], f[5]);
        unpack64(aB[3], f[6], f[7]);
        const __half2 p0 = __floats2half2_rn(f[0], f[1]);
        const __half2 p1 = __floats2half2_rn(f[2], f[3]);
        const __half2 p2 = __floats2half2_rn(f[4], f[5]);
        const __half2 p3 = __floats2half2_rn(f[6], f[7]);
        gAgg[(size_t)nB * 16 + s] =
            make_uint4(*(const unsigned*)&p0, *(const unsigned*)&p1,
                       *(const unsigned*)&p2, *(const unsigned*)&p3);
    }
}

// ---- GEMM kernel: stream agg tile -> smem -> HMMA -> bias+relu -> out ----
__global__ void __launch_bounds__(THREADS, 4)
gcn_gemm(const float* __restrict__ bias, float* __restrict__ out, int N)
{
    extern __shared__ char smem[];
    const int tid   = threadIdx.x;
    const int wid   = tid >> 5;
    const int lane  = tid & 31;
    const int node0 = blockIdx.x * NPB;

    // load A tile (128 rows x 16 uint4) coalesced, store swizzled
    #pragma unroll
    for (int i = 0; i < 8; i++) {
        const int idx = i * 256 + tid;           // 0..2047
        const int row = idx >> 4;
        const int ss  = idx & 15;
        const uint4 v = __ldg(gAgg + (size_t)node0 * 16 + idx);   // MAXN-padded: safe
        *(uint4*)(smem + SM_A + a_off(row, ss)) = v;
    }
    __syncthreads();

    const int m0 = wid * 16;
    const int mi = lane >> 3;
    const int mr = lane & 7;
    const int arow = m0 + ((mi & 1) << 3) + mr;
    const uint32_t sA = smem_u32(smem + SM_A);
    const int bq = (lane >> 2) * 4 + (lane & 3);

    const int r0 = node0 + m0 + (lane >> 2);
    const int cb = 2 * (lane & 3);

    #pragma unroll
    for (int half = 0; half < 2; half++) {
        float acc[8][4];
        #pragma unroll
        for (int nc = 0; nc < 8; nc++)
            acc[nc][0] = acc[nc][1] = acc[nc][2] = acc[nc][3] = 0.f;

        #pragma unroll
        for (int kc = 0; kc < 8; kc++) {
            const int chunk = kc * 2 + (mi >> 1);
            const uint32_t aaddr = (uint32_t)a_off(arow, chunk);
            uint32_t a0, a1, a2, a3;
            ldmatrix_x4(a0, a1, a2, a3, sA + aaddr);

            const uint4* __restrict__ bp = gB + kc * 512 + half * 256 + bq;
            #pragma unroll
            for (int nc = 0; nc < 8; nc++) {
                const uint4 v = __ldg(bp + nc * 32);
                mma_f16(acc[nc][0], acc[nc][1], acc[nc][2], acc[nc][3],
                        a0, a1, a2, a3, v.x, v.y);
                mma_f16(acc[nc][0], acc[nc][1], acc[nc][2], acc[nc][3],
                        a0, a1, a2, a3, v.z, v.w);
            }
        }

        #pragma unroll
        for (int nc = 0; nc < 8; nc++) {
            const int col = half * 64 + nc * 8 + cb;
            const float2 bv = __ldg((const float2*)(bias + col));
            if (r0 < N) {
                float2 o0;
                o0.x = fmaxf(acc[nc][0] + bv.x, 0.f);
                o0.y = fmaxf(acc[nc][1] + bv.y, 0.f);
                *(float2*)(out + (size_t)r0 * DD + col) = o0;
            }
            if (r0 + 8 < N) {
                float2 o1;
                o1.x = fmaxf(acc[nc][2] + bv.x, 0.f);
                o1.y = fmaxf(acc[nc][3] + bv.y, 0.f);
                *(float2*)(out + (size_t)(r0 + 8) * DD + col) = o1;
            }
        }
    }
}

extern "C" void kernel_launch(void* const* d_in, const int* in_sizes, int n_in,
                              void* d_out, int out_size)
{
    const float* feat = (const float*)d_in[0];
    const int*   rows = (const int*)d_in[1];
    const char*  cols = (const char*)d_in[2];
    const float* ew   = (const float*)d_in[3];
    const float* Wg   = (const float*)d_in[4];
    const float* bias = (const float*)d_in[5];
    float*       out  = (float*)d_out;

    const int N = in_sizes[0] / DD;

    const int total16   = N * DD / 16;
    const int nblk_feat = (total16 + 255) / 256;
    const int nblk_w    = (8 * 128 * 4 + 255) / 256;
    const int nblk_e    = (N + 15) / 16;                 // 16 nodes per 256-thr block
    prep_all<<<nblk_feat + nblk_w + nblk_e, 256>>>(feat, Wg, rows, cols, ew,
                                                   nblk_feat, nblk_w, total16, N);

    gcn_gather<<<(N + 15) / 16, 128>>>(N);

    cudaFuncSetAttribute(gcn_gemm, cudaFuncAttributeMaxDynamicSharedMemorySize, SM_TOTAL);
    gcn_gemm<<<(N + NPB - 1) / NPB, THREADS, SM_TOTAL>>>(bias, out, N);
}